// round 2
// baseline (speedup 1.0000x reference)
#include <cuda_runtime.h>
#include <cstdint>

#define N_   32
#define C_   256
#define H_   56
#define W_   56
#define HW_  3136
#define CW_  64        // C/4 packed int8 words per pixel
#define EPS_ 1e-5f

// ---------------- device scratch (no cudaMalloc allowed) ----------------
__device__ int   d_t1p[N_ * CW_ * HW_];                 // sign(x+b11) packed, [n][cw][h][w]
__device__ int   d_t2p[N_ * CW_ * HW_];                 // sign(out1+b21) packed
__device__ float d_out1[(size_t)N_ * C_ * HW_];         // out1 (fp32, NCHW)
__device__ int   d_wp3[9 * CW_ * C_];                   // packed sign(w3): [tap][cw][o]
__device__ int   d_wp1[CW_ * C_];                       // packed sign(w1): [cw][o]
__device__ float d_scale1[C_], d_sh1[C_], d_scale2[C_], d_sh2[C_];

__device__ __forceinline__ int sgn8(float v) { return (v > 0.f) - (v < 0.f); }

// ---------------- kernel 1: weight prep ----------------
__global__ void prep_kernel(const float* __restrict__ w3, const float* __restrict__ w1,
                            const float* __restrict__ g1, const float* __restrict__ be1,
                            const float* __restrict__ m1, const float* __restrict__ v1,
                            const float* __restrict__ g2, const float* __restrict__ be2,
                            const float* __restrict__ m2, const float* __restrict__ v2)
{
    __shared__ float red[256];
    const int o = blockIdx.x, tid = threadIdx.x;
    const float* w3o = w3 + (size_t)o * 2304;
    const float* w1o = w1 + (size_t)o * 256;

    // alpha3 = mean |w3[o]|
    float s = 0.f;
    for (int k = tid; k < 2304; k += 256) s += fabsf(w3o[k]);
    red[tid] = s; __syncthreads();
    for (int st = 128; st > 0; st >>= 1) { if (tid < st) red[tid] += red[tid + st]; __syncthreads(); }
    const float alpha3 = red[0] * (1.f / 2304.f);
    __syncthreads();

    // alpha1 = mean |w1[o]|
    red[tid] = fabsf(w1o[tid]); __syncthreads();
    for (int st = 128; st > 0; st >>= 1) { if (tid < st) red[tid] += red[tid + st]; __syncthreads(); }
    const float alpha1 = red[0] * (1.f / 256.f);

    // pack sign(w3) -> d_wp3[tap][cw][o]
    for (int idx = tid; idx < 576; idx += 256) {
        const int tap = idx % 9, cw = idx / 9;
        int wv = 0;
        #pragma unroll
        for (int j = 0; j < 4; ++j) {
            float v = w3o[(cw * 4 + j) * 9 + tap];
            wv |= (sgn8(v) & 0xFF) << (8 * j);
        }
        d_wp3[(tap * 64 + cw) * 256 + o] = wv;
    }
    // pack sign(w1) -> d_wp1[cw][o]
    if (tid < 64) {
        int wv = 0;
        #pragma unroll
        for (int j = 0; j < 4; ++j) {
            float v = w1o[tid * 4 + j];
            wv |= (sgn8(v) & 0xFF) << (8 * j);
        }
        d_wp1[tid * 256 + o] = wv;
    }
    if (tid == 0) {
        const float inv1 = g1[o] * rsqrtf(v1[o] + EPS_);
        d_scale1[o] = alpha3 * inv1;
        d_sh1[o]    = be1[o] - m1[o] * inv1;
        const float inv2 = g2[o] * rsqrtf(v2[o] + EPS_);
        d_scale2[o] = alpha1 * inv2;
        d_sh2[o]    = be2[o] - m2[o] * inv2;
    }
}

// ---------------- kernel 2: binarize + pack input ----------------
__global__ void pack_in_kernel(const float* __restrict__ x, const float* __restrict__ b11)
{
    const int idx = blockIdx.x * 256 + threadIdx.x;     // word index over [n][cw][s]
    if (idx >= N_ * CW_ * HW_) return;
    const int s  = idx % HW_;
    const int t  = idx / HW_;
    const int cw = t % CW_;
    const int n  = t / CW_;
    const float* xb = x + ((size_t)(n * C_ + cw * 4)) * HW_ + s;
    int w = 0;
    #pragma unroll
    for (int j = 0; j < 4; ++j) {
        float v = xb[(size_t)j * HW_] + __ldg(&b11[cw * 4 + j]);
        w |= (sgn8(v) & 0xFF) << (8 * j);
    }
    d_t1p[idx] = w;
}

// ---------------- kernel 3: binary 3x3 conv + BN + residual + PReLU + repack ----------------
// tile: 64 pixels (8x8 patch) x 64 out channels, each thread 4px x 4oc
__global__ void __launch_bounds__(256)
conv3x3_kernel(const float* __restrict__ x,
               const float* __restrict__ b12, const float* __restrict__ b13,
               const float* __restrict__ a1,  const float* __restrict__ b21)
{
    __shared__ __align__(16) int As[6464];   // halo 10x10 x 64 words, idx = y*644 + x*64 + cw
    __shared__ __align__(16) int Bs[4096];   // [cw][o]  (64 x 64)

    int bid = blockIdx.x;
    const int oc = bid & 3;      int t = bid >> 2;
    const int px0 = (t % 7) * 8; t /= 7;
    const int py0 = (t % 7) * 8; const int n = t / 7;
    const int o0 = oc << 6;
    const int tid = threadIdx.x;

    // load halo (zero padding outside image)
    const int* t1 = d_t1p + (size_t)n * (CW_ * HW_);
    for (int i = tid; i < 6400; i += 256) {
        const int cw = i / 100;
        const int r  = i - cw * 100;
        const int y  = r / 10, xq = r - (r / 10) * 10;
        const int gy = py0 - 1 + y, gx = px0 - 1 + xq;
        int v = 0;
        if ((unsigned)gy < 56u && (unsigned)gx < 56u)
            v = t1[cw * HW_ + gy * 56 + gx];
        As[y * 644 + xq * 64 + cw] = v;
    }

    int acc[4][4] = {};
    const int pp = tid & 15, op = tid >> 4;
    const int p0 = pp << 2;
    const int py = p0 >> 3, pxr = p0 & 7;     // 4 pixels: (py, pxr..pxr+3)

    for (int tap = 0; tap < 9; ++tap) {
        const int ky = (tap * 11) >> 5;       // tap/3 for 0..8
        const int kx = tap - ky * 3;
        __syncthreads();
        const int* wp = d_wp3 + tap * 64 * 256 + o0;
        for (int i = tid; i < 4096; i += 256)
            Bs[i] = wp[(i >> 6) * 256 + (i & 63)];
        __syncthreads();

        const int* arow = &As[(py + ky) * 644 + (pxr + kx) * 64];
        #pragma unroll
        for (int c4 = 0; c4 < 16; ++c4) {
            int4 av[4], bv[4];
            #pragma unroll
            for (int i = 0; i < 4; ++i) av[i] = *(const int4*)&arow[i * 64 + c4 * 4];
            #pragma unroll
            for (int c = 0; c < 4; ++c) bv[c] = *(const int4*)&Bs[(c4 * 4 + c) * 64 + (op << 2)];
            #pragma unroll
            for (int i = 0; i < 4; ++i) {
                const int* ai = (const int*)&av[i];
                #pragma unroll
                for (int c = 0; c < 4; ++c) {
                    const int* bc = (const int*)&bv[c];
                    acc[i][0] = __dp4a(ai[c], bc[0], acc[i][0]);
                    acc[i][1] = __dp4a(ai[c], bc[1], acc[i][1]);
                    acc[i][2] = __dp4a(ai[c], bc[2], acc[i][2]);
                    acc[i][3] = __dp4a(ai[c], bc[3], acc[i][3]);
                }
            }
        }
    }

    // fused epilogue: out1 = prelu(x + bn(conv) + b12, a1) + b13 ; t2 = sign(out1 + b21)
    const int gy = py0 + py, gx0 = px0 + pxr;
    const size_t pixoff = (size_t)gy * 56 + gx0;
    int packw[4] = {0, 0, 0, 0};
    #pragma unroll
    for (int j = 0; j < 4; ++j) {
        const int o = o0 + (op << 2) + j;
        const float sc  = d_scale1[o], sh = d_sh1[o];
        const float B12 = __ldg(&b12[o]), B13 = __ldg(&b13[o]);
        const float A1  = __ldg(&a1[o]),  B21 = __ldg(&b21[o]);
        const size_t base = ((size_t)n * C_ + o) * HW_ + pixoff;
        const float4 xv = *(const float4*)(x + base);
        const float xs[4] = { xv.x, xv.y, xv.z, xv.w };
        float vout[4];
        #pragma unroll
        for (int i = 0; i < 4; ++i) {
            float u = xs[i] + (float)acc[i][j] * sc + sh + B12;
            float r = (u > 0.f ? u : u * A1) + B13;
            vout[i] = r;
            packw[i] |= (sgn8(r + B21) & 0xFF) << (8 * j);
        }
        *(float4*)(d_out1 + base) = make_float4(vout[0], vout[1], vout[2], vout[3]);
    }
    const int cw2 = (o0 >> 2) + op;      // this thread's 4 channels are consecutive -> one packed word/pixel
    *(int4*)(d_t2p + ((size_t)n * CW_ + cw2) * HW_ + pixoff) =
        make_int4(packw[0], packw[1], packw[2], packw[3]);
}

// ---------------- kernel 4: binary 1x1 conv + BN + residual + PReLU ----------------
__global__ void __launch_bounds__(256)
conv1x1_kernel(const float* __restrict__ b22, const float* __restrict__ b23,
               const float* __restrict__ a2, float* __restrict__ out)
{
    __shared__ __align__(16) int As[4096];   // [cw][p]
    __shared__ __align__(16) int Bs[4096];   // [cw][o]

    int bid = blockIdx.x;
    const int oc = bid & 3; const int pb = bid >> 2;
    const int n  = pb / 49; const int p0 = (pb - n * 49) << 6;
    const int o0 = oc << 6;
    const int tid = threadIdx.x;

    for (int i = tid; i < 4096; i += 256) {
        const int cw = i >> 6, q = i & 63;
        As[i] = d_t2p[((size_t)n * CW_ + cw) * HW_ + p0 + q];
        Bs[i] = d_wp1[cw * 256 + o0 + q];
    }
    __syncthreads();

    int acc[4][4] = {};
    const int pp = tid & 15, op = tid >> 4;

    #pragma unroll
    for (int c4 = 0; c4 < 16; ++c4) {
        int4 av[4], bv[4];
        #pragma unroll
        for (int c = 0; c < 4; ++c) {
            av[c] = *(const int4*)&As[(c4 * 4 + c) * 64 + (pp << 2)];  // 4 pixels for this cw
            bv[c] = *(const int4*)&Bs[(c4 * 4 + c) * 64 + (op << 2)];  // 4 outch for this cw
        }
        #pragma unroll
        for (int c = 0; c < 4; ++c) {
            const int* ac = (const int*)&av[c];
            const int* bc = (const int*)&bv[c];
            #pragma unroll
            for (int i = 0; i < 4; ++i) {
                acc[i][0] = __dp4a(ac[i], bc[0], acc[i][0]);
                acc[i][1] = __dp4a(ac[i], bc[1], acc[i][1]);
                acc[i][2] = __dp4a(ac[i], bc[2], acc[i][2]);
                acc[i][3] = __dp4a(ac[i], bc[3], acc[i][3]);
            }
        }
    }

    // epilogue: out2 = prelu(bn(conv2) + out1 + b22, a2) + b23
    #pragma unroll
    for (int j = 0; j < 4; ++j) {
        const int o = o0 + (op << 2) + j;
        const float sc  = d_scale2[o], sh = d_sh2[o];
        const float B22 = __ldg(&b22[o]), B23 = __ldg(&b23[o]), A2 = __ldg(&a2[o]);
        const size_t base = ((size_t)n * C_ + o) * HW_ + p0 + (pp << 2);
        const float4 o1v = *(const float4*)(d_out1 + base);
        const float o1s[4] = { o1v.x, o1v.y, o1v.z, o1v.w };
        float vout[4];
        #pragma unroll
        for (int i = 0; i < 4; ++i) {
            float u = (float)acc[i][j] * sc + sh + o1s[i] + B22;
            vout[i] = (u > 0.f ? u : u * A2) + B23;
        }
        *(float4*)(out + base) = make_float4(vout[0], vout[1], vout[2], vout[3]);
    }
}

// ---------------- launch ----------------
extern "C" void kernel_launch(void* const* d_in, const int* in_sizes, int n_in,
                              void* d_out, int out_size)
{
    (void)in_sizes; (void)n_in; (void)out_size;
    const float* x   = (const float*)d_in[0];
    const float* w3  = (const float*)d_in[1];
    const float* w1  = (const float*)d_in[2];
    const float* b11 = (const float*)d_in[3];
    const float* b12 = (const float*)d_in[4];
    const float* b13 = (const float*)d_in[5];
    const float* b21 = (const float*)d_in[6];
    const float* b22 = (const float*)d_in[7];
    const float* b23 = (const float*)d_in[8];
    const float* g1  = (const float*)d_in[9];
    const float* be1 = (const float*)d_in[10];
    const float* m1  = (const float*)d_in[11];
    const float* v1  = (const float*)d_in[12];
    const float* g2  = (const float*)d_in[13];
    const float* be2 = (const float*)d_in[14];
    const float* m2  = (const float*)d_in[15];
    const float* v2  = (const float*)d_in[16];
    const float* a1  = (const float*)d_in[17];
    const float* a2  = (const float*)d_in[18];

    prep_kernel<<<C_, 256>>>(w3, w1, g1, be1, m1, v1, g2, be2, m2, v2);
    pack_in_kernel<<<(N_ * CW_ * HW_) / 256, 256>>>(x, b11);
    conv3x3_kernel<<<N_ * 49 * 4, 256>>>(x, b12, b13, a1, b21);
    conv1x1_kernel<<<N_ * 49 * 4, 256>>>(b22, b23, a2, (float*)d_out);
}